// round 5
// baseline (speedup 1.0000x reference)
#include <cuda_runtime.h>

// ---------------- problem constants ----------------
// kv:  (256, 128, 192)   q: (256, 512, 96)
// w_kv:(192,384) b_kv:(384)  w_q:(96,192) b_q:(192)
// w_proj:(192,96) b_proj:(96)
// bias_table:(3375,6)  rel_index:(512,128) int32
// out: (256, 512, 96) fp32

// ---------------- scratch (device globals, allowed) ----------------
__device__ float g_kvp[32768u * 384u];    // kv proj   [B*128, 384]
__device__ float g_qp [131072u * 192u];   // q proj    [B*512, 192] (scaled)
__device__ float g_att[131072u * 192u];   // attn out  [B*512, 192]
__device__ float g_bias[6u * 512u * 128u];// expanded bias [h][q][k]

// ---------------- bias expansion ----------------
__global__ __launch_bounds__(256) void bias_expand_kernel(
    const float* __restrict__ table, const int* __restrict__ rel)
{
    int idx = blockIdx.x * 256 + threadIdx.x;       // 6*512*128 = 393216
    if (idx >= 6 * 512 * 128) return;
    int h  = idx >> 16;                              // 512*128 = 65536
    int qk = idx & 65535;
    g_bias[idx] = table[rel[qk] * 6 + h];
}

// ---------------- generic GEMM: C = (A @ W + bias) * scale ----------------
// A: [M,K] row-major, W: [K,N] row-major, bias: [N]
// tile 128x128, k-tile 16, 256 threads, 8x8 micro-tile per thread.
// M % 128 == 0, K % 16 == 0, N % 4 == 0 (cols masked against N).
__global__ __launch_bounds__(256) void gemm_bias_kernel(
    const float* __restrict__ A, const float* __restrict__ W,
    const float* __restrict__ bias, float* __restrict__ C,
    int M, int K, int N, float scale)
{
    __shared__ float As[16][132];   // As[k][m] (transposed A tile)
    __shared__ float Bs[16][132];   // Bs[k][n]

    const int tid = threadIdx.x;
    const int bm = blockIdx.y * 128;
    const int bn = blockIdx.x * 128;
    const int tx = tid & 15;
    const int ty = tid >> 4;

    float acc[8][8];
#pragma unroll
    for (int i = 0; i < 8; i++)
#pragma unroll
        for (int j = 0; j < 8; j++) acc[i][j] = 0.f;

    for (int k0 = 0; k0 < K; k0 += 16) {
        // load A tile (128 rows x 16 k) as float4 along k, store transposed
#pragma unroll
        for (int i = 0; i < 2; i++) {
            int lin = tid + i * 256;            // 0..511
            int row = lin >> 2;                 // 0..127
            int kc  = (lin & 3) << 2;           // 0,4,8,12
            const float4 va = *(const float4*)(A + (size_t)(bm + row) * K + (k0 + kc));
            As[kc + 0][row] = va.x;
            As[kc + 1][row] = va.y;
            As[kc + 2][row] = va.z;
            As[kc + 3][row] = va.w;
        }
        // load B tile (16 k x 128 n) as float4 along n
#pragma unroll
        for (int i = 0; i < 2; i++) {
            int lin = tid + i * 256;
            int kk = lin >> 5;                  // 0..15
            int nc = (lin & 31) << 2;           // 0..124
            float4 vb;
            if (bn + nc < N)
                vb = *(const float4*)(W + (size_t)(k0 + kk) * N + (bn + nc));
            else
                vb = make_float4(0.f, 0.f, 0.f, 0.f);
            *(float4*)&Bs[kk][nc] = vb;
        }
        __syncthreads();

#pragma unroll
        for (int k = 0; k < 16; k++) {
            float a[8], b[8];
            *(float4*)&a[0] = *(const float4*)&As[k][ty * 8];
            *(float4*)&a[4] = *(const float4*)&As[k][ty * 8 + 4];
            *(float4*)&b[0] = *(const float4*)&Bs[k][tx * 8];
            *(float4*)&b[4] = *(const float4*)&Bs[k][tx * 8 + 4];
#pragma unroll
            for (int i = 0; i < 8; i++)
#pragma unroll
                for (int j = 0; j < 8; j++)
                    acc[i][j] = fmaf(a[i], b[j], acc[i][j]);
        }
        __syncthreads();
    }

    // epilogue: add bias, scale, store (cols masked vs N)
#pragma unroll
    for (int i = 0; i < 8; i++) {
        int row = bm + ty * 8 + i;
#pragma unroll
        for (int j = 0; j < 8; j += 4) {
            int col = bn + tx * 8 + j;
            if (col < N) {
                float4 r;
                r.x = (acc[i][j + 0] + bias[col + 0]) * scale;
                r.y = (acc[i][j + 1] + bias[col + 1]) * scale;
                r.z = (acc[i][j + 2] + bias[col + 2]) * scale;
                r.w = (acc[i][j + 3] + bias[col + 3]) * scale;
                *(float4*)(C + (size_t)row * N + col) = r;
            }
        }
    }
}

// ---------------- fused attention per (b, h) ----------------
// Per block: one (batch, head). K/V tiles (128x32) in XOR-swizzled smem
// (conflict-free loads AND stores, zero padding). 8 warps, each warp owns
// 64 query rows, processed 8 at a time. Softmax+AV done in two 4-row halves
// so P staging fits; total static smem = 48 KB exactly.
__global__ __launch_bounds__(256) void attn_kernel(
    const float* __restrict__ kvp,    // [B*128, 384]
    const float* __restrict__ qp,     // [B*512, 192]  (pre-scaled)
    float* __restrict__ outp)         // [B*512, 192]
{
    __shared__ float Kt[32 * 128];    // Kt[d][n ^ d]            (scalar swizzle)
    __shared__ float Vt[32 * 128];    // Vt[d][((n>>2)^d)*4+n&3] (float4-chunk swizzle)
    __shared__ float Ps[8 * 4 * 128]; // per-warp P staging (4 rows)

    const int tid  = threadIdx.x;
    const int w    = tid >> 5;
    const int lane = tid & 31;
    const int b = blockIdx.x / 6;
    const int h = blockIdx.x % 6;

    // ---- load K (d-major, swizzled) and V (float4-chunk swizzled) ----
#pragma unroll
    for (int i = 0; i < 16; i++) {
        int n = w + 8 * i;                                   // 0..127
        const float* src = kvp + (size_t)(b * 128 + n) * 384 + h * 32;
        float kval = src[lane];          // K[n][d=lane]
        float vval = src[192 + lane];    // V[n][d=lane]
        Kt[lane * 128 + (n ^ lane)] = kval;
        Vt[lane * 128 + ((((unsigned)n >> 2) ^ lane) << 2) + (n & 3)] = vval;
    }
    __syncthreads();

    const float* qb   = qp  + (size_t)(b * 512) * 192 + h * 32;
    const float* bb   = g_bias + (size_t)h * 512 * 128;
    float*       ob   = outp + (size_t)(b * 512) * 192 + h * 32;
    float*       myps = Ps + w * 4 * 128;

    for (int it = 0; it < 8; it++) {
        const int r0 = (w << 6) + (it << 3);   // 8 query rows for this warp

        // q rows in registers, distributed: lane holds q[r0+j][d=lane]
        float qreg[8];
#pragma unroll
        for (int j = 0; j < 8; j++)
            qreg[j] = qb[(size_t)(r0 + j) * 192 + lane];

        // ---- QK^T: acc[qi][j] = s(r0+qi, key = lane + 32*j) ----
        float acc[8][4];
#pragma unroll
        for (int qi = 0; qi < 8; qi++)
#pragma unroll
            for (int j = 0; j < 4; j++) acc[qi][j] = 0.f;

#pragma unroll 8
        for (int d = 0; d < 32; d++) {
            int kb = d * 128 + (lane ^ d);
            float k0 = Kt[kb];
            float k1 = Kt[kb + 32];
            float k2 = Kt[kb + 64];
            float k3 = Kt[kb + 96];
#pragma unroll
            for (int qi = 0; qi < 8; qi++) {
                float qv = __shfl_sync(0xffffffffu, qreg[qi], d);
                acc[qi][0] = fmaf(qv, k0, acc[qi][0]);
                acc[qi][1] = fmaf(qv, k1, acc[qi][1]);
                acc[qi][2] = fmaf(qv, k2, acc[qi][2]);
                acc[qi][3] = fmaf(qv, k3, acc[qi][3]);
            }
        }

        // ---- bias + softmax + AV, 4 rows at a time ----
#pragma unroll
        for (int half = 0; half < 2; half++) {
#pragma unroll
            for (int qi = 0; qi < 4; qi++) {
                int qg = half * 4 + qi;
                const float* bq = bb + (size_t)(r0 + qg) * 128;
                float s0 = acc[qg][0] + bq[lane];
                float s1 = acc[qg][1] + bq[lane + 32];
                float s2 = acc[qg][2] + bq[lane + 64];
                float s3 = acc[qg][3] + bq[lane + 96];
                float m = fmaxf(fmaxf(s0, s1), fmaxf(s2, s3));
#pragma unroll
                for (int o = 16; o > 0; o >>= 1)
                    m = fmaxf(m, __shfl_xor_sync(0xffffffffu, m, o));
                float e0 = __expf(s0 - m);
                float e1 = __expf(s1 - m);
                float e2 = __expf(s2 - m);
                float e3 = __expf(s3 - m);
                float sum = e0 + e1 + e2 + e3;
#pragma unroll
                for (int o = 16; o > 0; o >>= 1)
                    sum += __shfl_xor_sync(0xffffffffu, sum, o);
                float inv = 1.0f / sum;
                myps[qi * 128 + lane]      = e0 * inv;
                myps[qi * 128 + lane + 32] = e1 * inv;
                myps[qi * 128 + lane + 64] = e2 * inv;
                myps[qi * 128 + lane + 96] = e3 * inv;
            }
            __syncwarp();

            // AV: out[row][d=lane] = sum_k P[row][k] * V[k][lane]
            float o0 = 0.f, o1 = 0.f, o2 = 0.f, o3 = 0.f;
#pragma unroll 8
            for (int kc4 = 0; kc4 < 32; kc4++) {
                float4 v4 = *(const float4*)&Vt[((lane << 5) + (kc4 ^ lane)) << 2];
                int kb = kc4 << 2;
                float4 p0 = *(const float4*)&myps[0 * 128 + kb];
                float4 p1 = *(const float4*)&myps[1 * 128 + kb];
                float4 p2 = *(const float4*)&myps[2 * 128 + kb];
                float4 p3 = *(const float4*)&myps[3 * 128 + kb];
                o0 += p0.x * v4.x + p0.y * v4.y + p0.z * v4.z + p0.w * v4.w;
                o1 += p1.x * v4.x + p1.y * v4.y + p1.z * v4.z + p1.w * v4.w;
                o2 += p2.x * v4.x + p2.y * v4.y + p2.z * v4.z + p2.w * v4.w;
                o3 += p3.x * v4.x + p3.y * v4.y + p3.z * v4.z + p3.w * v4.w;
            }
            ob[(size_t)(r0 + half * 4 + 0) * 192 + lane] = o0;
            ob[(size_t)(r0 + half * 4 + 1) * 192 + lane] = o1;
            ob[(size_t)(r0 + half * 4 + 2) * 192 + lane] = o2;
            ob[(size_t)(r0 + half * 4 + 3) * 192 + lane] = o3;
            __syncwarp();
        }
    }
}

// ---------------- launch ----------------
extern "C" void kernel_launch(void* const* d_in, const int* in_sizes, int n_in,
                              void* d_out, int out_size)
{
    const float* kv         = (const float*)d_in[0];
    const float* q          = (const float*)d_in[1];
    const float* w_kv       = (const float*)d_in[2];
    const float* b_kv       = (const float*)d_in[3];
    const float* w_q        = (const float*)d_in[4];
    const float* b_q        = (const float*)d_in[5];
    const float* w_proj     = (const float*)d_in[6];
    const float* b_proj     = (const float*)d_in[7];
    const float* bias_table = (const float*)d_in[8];
    const int*   rel_index  = (const int*)  d_in[9];
    float* out = (float*)d_out;

    float *p_kvp, *p_qp, *p_att;
    cudaGetSymbolAddress((void**)&p_kvp, g_kvp);
    cudaGetSymbolAddress((void**)&p_qp,  g_qp);
    cudaGetSymbolAddress((void**)&p_att, g_att);

    const float qscale = 0.17677669529663687f;  // 1/sqrt(32)

    // bias expansion (independent of batch data)
    bias_expand_kernel<<<1536, 256>>>(bias_table, rel_index);

    // kv projection: (32768 x 192) @ (192 x 384) + b_kv
    gemm_bias_kernel<<<dim3(3, 256), 256>>>(kv, w_kv, b_kv, p_kvp,
                                            32768, 192, 384, 1.0f);
    // q projection (scaled): (131072 x 96) @ (96 x 192) + b_q
    gemm_bias_kernel<<<dim3(2, 1024), 256>>>(q, w_q, b_q, p_qp,
                                             131072, 96, 192, qscale);
    // fused attention per (batch, head)
    attn_kernel<<<256 * 6, 256>>>(p_kvp, p_qp, p_att);

    // output projection: (131072 x 192) @ (192 x 96) + b_proj
    gemm_bias_kernel<<<dim3(1, 1024), 256>>>(p_att, w_proj, b_proj, out,
                                             131072, 192, 96, 1.0f);
}